// round 4
// baseline (speedup 1.0000x reference)
#include <cuda_runtime.h>
#include <cstdint>

#define D   1024
#define NN  64
#define EE  1024
#define DC4 (D/4)

// ---------------- scratch (no allocations allowed) ----------------
__device__ float g_vctx[NN*D], g_vctx2[NN*D], g_vprod[NN*D], g_vj[NN*D];
__device__ float g_vjWs[NN*D], g_vjWo[NN*D], g_u[NN*D], g_vv[NN*D];
__device__ float g_ctx1[NN*D], g_ctx2[NN*D];
__device__ float g_rc[EE*D], g_rc2[EE*D], g_tprc[EE*D], g_rj[EE*D], g_relj[EE*D];
__device__ float g_Ys[EE*D], g_Yo[EE*D];
__device__ float g_ssbj[EE], g_sobj[EE], g_wsbj[EE], g_wobj[EE];
__device__ float g_W14[D*D], g_W24[D*D], g_WjA[D*D], g_WjB[D*D];

// ---------------- SGEMM: C[m,n] = sum_k A[m,k]*B[n,k]  (+= if acc) -------
// A row-major (lda), B row-major (ldb) -> computes A @ B^T.
template<int BM, int BN, int BK, int TM, int TN>
__global__ void __launch_bounds__(256) sgemm_nt(
    const float* __restrict__ A, int lda,
    const float* __restrict__ B, int ldb,
    float* __restrict__ C, int ldc,
    int K, int acc)
{
    __shared__ float As[BK][BM];
    __shared__ float Bs[BK][BN];
    const int tid = threadIdx.x;
    const int tx  = tid % (BN / TN);
    const int ty  = tid / (BN / TN);
    const int bm0 = blockIdx.y * BM;
    const int bn0 = blockIdx.x * BN;

    float accr[TM][TN];
#pragma unroll
    for (int i = 0; i < TM; i++)
#pragma unroll
        for (int j = 0; j < TN; j++) accr[i][j] = 0.f;

    for (int k0 = 0; k0 < K; k0 += BK) {
#pragma unroll
        for (int i = tid * 4; i < BM * BK; i += 256 * 4) {
            int lr = i / BK, lc = i % BK;
            float4 v = *(const float4*)(A + (size_t)(bm0 + lr) * lda + k0 + lc);
            As[lc + 0][lr] = v.x; As[lc + 1][lr] = v.y;
            As[lc + 2][lr] = v.z; As[lc + 3][lr] = v.w;
        }
#pragma unroll
        for (int i = tid * 4; i < BN * BK; i += 256 * 4) {
            int lr = i / BK, lc = i % BK;
            float4 v = *(const float4*)(B + (size_t)(bn0 + lr) * ldb + k0 + lc);
            Bs[lc + 0][lr] = v.x; Bs[lc + 1][lr] = v.y;
            Bs[lc + 2][lr] = v.z; Bs[lc + 3][lr] = v.w;
        }
        __syncthreads();
#pragma unroll
        for (int k = 0; k < BK; k++) {
            float a[TM], b[TN];
#pragma unroll
            for (int i = 0; i < TM; i += 4)
                *(float4*)&a[i] = *(const float4*)&As[k][ty * TM + i];
#pragma unroll
            for (int j = 0; j < TN; j += 4)
                *(float4*)&b[j] = *(const float4*)&Bs[k][tx * TN + j];
#pragma unroll
            for (int i = 0; i < TM; i++)
#pragma unroll
                for (int j = 0; j < TN; j++)
                    accr[i][j] += a[i] * b[j];
        }
        __syncthreads();
    }
#pragma unroll
    for (int i = 0; i < TM; i++) {
        int row = bm0 + ty * TM + i;
#pragma unroll
        for (int j = 0; j < TN; j += 4) {
            float* cp = C + (size_t)row * ldc + bn0 + tx * TN + j;
            float4 out;
            if (acc) {
                float4 old = *(const float4*)cp;
                out.x = old.x + accr[i][j + 0];
                out.y = old.y + accr[i][j + 1];
                out.z = old.z + accr[i][j + 2];
                out.w = old.w + accr[i][j + 3];
            } else {
                out.x = accr[i][j + 0]; out.y = accr[i][j + 1];
                out.z = accr[i][j + 2]; out.w = accr[i][j + 3];
            }
            *(float4*)cp = out;
        }
    }
}

// ---------------- small kernels ----------------
__global__ void prep_weights(const float* __restrict__ Wrj,
                             const float* __restrict__ Wj,
                             float* __restrict__ W14, float* __restrict__ W24,
                             float* __restrict__ WjA, float* __restrict__ WjB)
{
    int gid = blockIdx.x * blockDim.x + threadIdx.x;   // D*D
    int o = gid >> 10, k = gid & (D - 1);
    const float* rr = Wrj + (size_t)o * (4 * D);
    W14[gid] = rr[k]        + rr[3 * D + k];
    W24[gid] = rr[D + k]    - rr[3 * D + k];
    const float* rj = Wj + (size_t)o * (4 * D);
    WjA[gid] = rj[k]        - rj[3 * D + k];
    WjB[gid] = rj[D + k]    + rj[3 * D + k];
}

__global__ void ewise_mul4(const float4* __restrict__ a,
                           const float4* __restrict__ b,
                           float4* __restrict__ o, int n4)
{
    int gid = blockIdx.x * blockDim.x + threadIdx.x;
    if (gid >= n4) return;
    float4 x = a[gid], y = b[gid];
    float4 r; r.x = x.x * y.x; r.y = x.y * y.y; r.z = x.z * y.z; r.w = x.w * y.w;
    o[gid] = r;
}

// relj[e,:] += vjWs[i(e),:] + vjWo[j(e),:]
__global__ void relj_add_nodes(const int* __restrict__ eidx,
                               const float4* __restrict__ vjWs,
                               const float4* __restrict__ vjWo,
                               float4* __restrict__ relj)
{
    int gid = blockIdx.x * blockDim.x + threadIdx.x;   // EE*DC4
    int e = gid >> 8, c4 = gid & (DC4 - 1);
    int idx = eidx[e];
    int i = idx >> 6, j = idx & 63;
    float4 r = relj[gid];
    float4 a = vjWs[i * DC4 + c4];
    float4 b = vjWo[j * DC4 + c4];
    r.x += a.x + b.x; r.y += a.y + b.y; r.z += a.z + b.z; r.w += a.w + b.w;
    relj[gid] = r;
}

// s_sbj[e] = <u[i(e)], Ys[e]>/32 ; s_obj[e] = <v[j(e)], Yo[e]>/32
__global__ void edge_scores(const int* __restrict__ eidx,
                            const float* __restrict__ u, const float* __restrict__ v,
                            const float* __restrict__ Ys, const float* __restrict__ Yo,
                            float* __restrict__ s_sbj, float* __restrict__ s_obj)
{
    int e = blockIdx.x;
    int idx = eidx[e];
    int i = idx >> 6, j = idx & 63;
    const float4* u4  = (const float4*)(u + (size_t)i * D);
    const float4* v4  = (const float4*)(v + (size_t)j * D);
    const float4* ys4 = (const float4*)(Ys + (size_t)e * D);
    const float4* yo4 = (const float4*)(Yo + (size_t)e * D);
    float ss = 0.f, so = 0.f;
    for (int c = threadIdx.x; c < DC4; c += blockDim.x) {
        float4 a = u4[c], b = ys4[c];
        ss += a.x * b.x + a.y * b.y + a.z * b.z + a.w * b.w;
        float4 a2 = v4[c], b2 = yo4[c];
        so += a2.x * b2.x + a2.y * b2.y + a2.z * b2.z + a2.w * b2.w;
    }
#pragma unroll
    for (int off = 16; off; off >>= 1) {
        ss += __shfl_xor_sync(0xffffffffu, ss, off);
        so += __shfl_xor_sync(0xffffffffu, so, off);
    }
    __shared__ float shs[4], sho[4];
    int warp = threadIdx.x >> 5, lane = threadIdx.x & 31;
    if (lane == 0) { shs[warp] = ss; sho[warp] = so; }
    __syncthreads();
    if (threadIdx.x == 0) {
        float a = shs[0] + shs[1] + shs[2] + shs[3];
        float b = sho[0] + sho[1] + sho[2] + sho[3];
        s_sbj[e] = a * 0.03125f;   // 1/sqrt(1024)
        s_obj[e] = b * 0.03125f;
    }
}

// blocks 0..63: row softmax of s_sbj (group by i); 64..127: col softmax of s_obj (by j)
__global__ void softmax_edges(const int* __restrict__ eidx,
                              const float* __restrict__ s_sbj, const float* __restrict__ s_obj,
                              float* __restrict__ w_sbj, float* __restrict__ w_obj)
{
    int mode = blockIdx.x >> 6;
    int node = blockIdx.x & 63;
    const float* s = mode ? s_obj : s_sbj;
    float* w = mode ? w_obj : w_sbj;
    int tid = threadIdx.x;                    // 128 threads
    __shared__ float red[128];
    float m = -1e30f;
    for (int e = tid; e < EE; e += 128) {
        int idx = eidx[e];
        int ne = mode ? (idx & 63) : (idx >> 6);
        if (ne == node) m = fmaxf(m, s[e]);
    }
    red[tid] = m; __syncthreads();
    for (int st = 64; st; st >>= 1) { if (tid < st) red[tid] = fmaxf(red[tid], red[tid + st]); __syncthreads(); }
    float mm = red[0]; __syncthreads();
    float z = 0.f;
    for (int e = tid; e < EE; e += 128) {
        int idx = eidx[e];
        int ne = mode ? (idx & 63) : (idx >> 6);
        if (ne == node) z += expf(s[e] - mm);
    }
    red[tid] = z; __syncthreads();
    for (int st = 64; st; st >>= 1) { if (tid < st) red[tid] += red[tid + st]; __syncthreads(); }
    float inv = 1.f / red[0];
    for (int e = tid; e < EE; e += 128) {
        int idx = eidx[e];
        int ne = mode ? (idx & 63) : (idx >> 6);
        if (ne == node) w[e] = expf(s[e] - mm) * inv;
    }
}

// blocks 0..63: ctx1[i] = sum_e(i(e)=i) w_sbj[e]*relj[e]; 64..127: ctx2[j] likewise
__global__ void ctx_accum(const int* __restrict__ eidx,
                          const float* __restrict__ w_sbj, const float* __restrict__ w_obj,
                          const float4* __restrict__ relj,
                          float4* __restrict__ ctx1, float4* __restrict__ ctx2)
{
    int part = blockIdx.x >> 6;
    int node = blockIdx.x & 63;
    int tid = threadIdx.x;                    // 256 threads = DC4
    __shared__ int   se[EE];
    __shared__ float sw[EE];
    for (int e = tid; e < EE; e += 256) {
        se[e] = eidx[e];
        sw[e] = part ? w_obj[e] : w_sbj[e];
    }
    __syncthreads();
    float4 acc = make_float4(0.f, 0.f, 0.f, 0.f);
    for (int e = 0; e < EE; e++) {
        int idx = se[e];
        int ne = part ? (idx & 63) : (idx >> 6);
        if (ne == node) {
            float wt = sw[e];
            float4 r = relj[(size_t)e * DC4 + tid];
            acc.x += wt * r.x; acc.y += wt * r.y; acc.z += wt * r.z; acc.w += wt * r.w;
        }
    }
    float4* out = part ? ctx2 : ctx1;
    out[node * DC4 + tid] = acc;
}

__global__ void init_bias(const float* __restrict__ b, float* __restrict__ out)
{
    int gid = blockIdx.x * blockDim.x + threadIdx.x;   // NN*D
    out[gid] = b[gid & (D - 1)];
}

// ---------------- host orchestration ----------------
static inline void gemm_big(const float* A, int lda, const float* B, int ldb,
                            float* C, int ldc, int M, int K, int acc)
{
    dim3 g(D / 64, M / 128);
    sgemm_nt<128, 64, 16, 8, 4><<<g, 256>>>(A, lda, B, ldb, C, ldc, K, acc);
}
static inline void gemm_small(const float* A, int lda, const float* B, int ldb,
                              float* C, int ldc, int K, int acc)
{
    dim3 g(D / 64, 1);   // M = 64
    sgemm_nt<64, 64, 16, 4, 4><<<g, 256>>>(A, lda, B, ldb, C, ldc, K, acc);
}

extern "C" void kernel_launch(void* const* d_in, const int* in_sizes, int n_in,
                              void* d_out, int out_size)
{
    (void)in_sizes; (void)n_in;
    const float* vf   = (const float*)d_in[0];
    const float* rvf  = (const float*)d_in[1];
    const int*   eidx = (const int*)  d_in[4];
    const float* W_sub   = (const float*)d_in[5];
    const float* W_obj   = (const float*)d_in[6];
    const float* W_r2s   = (const float*)d_in[7];
    const float* W_r2o   = (const float*)d_in[8];
    const float* W_joint = (const float*)d_in[9];
    const float* W_ctx   = (const float*)d_in[10];
    const float* W_ru    = (const float*)d_in[11];   // W_rel_update (D,3D)
    const float* W_rj    = (const float*)d_in[12];   // W_rel_joint  (D,4D)
    const float* W_rctx  = (const float*)d_in[13];   // (D,2D)
    const float* W_node  = (const float*)d_in[14];   // (D,2D)
    const float* b_node  = (const float*)d_in[15];
    const float* W_fac   = (const float*)d_in[16];   // (D,2D)

    void* p;
    cudaGetSymbolAddress(&p, g_vctx);  float* pvctx  = (float*)p;
    cudaGetSymbolAddress(&p, g_vctx2); float* pvctx2 = (float*)p;
    cudaGetSymbolAddress(&p, g_vprod); float* pvprod = (float*)p;
    cudaGetSymbolAddress(&p, g_vj);    float* pvj    = (float*)p;
    cudaGetSymbolAddress(&p, g_vjWs);  float* pvjWs  = (float*)p;
    cudaGetSymbolAddress(&p, g_vjWo);  float* pvjWo  = (float*)p;
    cudaGetSymbolAddress(&p, g_u);     float* pu     = (float*)p;
    cudaGetSymbolAddress(&p, g_vv);    float* pv     = (float*)p;
    cudaGetSymbolAddress(&p, g_ctx1);  float* pctx1  = (float*)p;
    cudaGetSymbolAddress(&p, g_ctx2);  float* pctx2  = (float*)p;
    cudaGetSymbolAddress(&p, g_rc);    float* prc    = (float*)p;
    cudaGetSymbolAddress(&p, g_rc2);   float* prc2   = (float*)p;
    cudaGetSymbolAddress(&p, g_tprc);  float* ptprc  = (float*)p;
    cudaGetSymbolAddress(&p, g_rj);    float* prj    = (float*)p;
    cudaGetSymbolAddress(&p, g_relj);  float* prelj  = (float*)p;
    cudaGetSymbolAddress(&p, g_Ys);    float* pYs    = (float*)p;
    cudaGetSymbolAddress(&p, g_Yo);    float* pYo    = (float*)p;
    cudaGetSymbolAddress(&p, g_ssbj);  float* pssbj  = (float*)p;
    cudaGetSymbolAddress(&p, g_sobj);  float* psobj  = (float*)p;
    cudaGetSymbolAddress(&p, g_wsbj);  float* pwsbj  = (float*)p;
    cudaGetSymbolAddress(&p, g_wobj);  float* pwobj  = (float*)p;
    cudaGetSymbolAddress(&p, g_W14);   float* pW14   = (float*)p;
    cudaGetSymbolAddress(&p, g_W24);   float* pW24   = (float*)p;
    cudaGetSymbolAddress(&p, g_WjA);   float* pWjA   = (float*)p;
    cudaGetSymbolAddress(&p, g_WjB);   float* pWjB   = (float*)p;

    // fold the 4-way concats into combined weights (once per launch)
    prep_weights<<<(D * D) / 256, 256>>>(W_rj, W_joint, pW14, pW24, pWjA, pWjB);

    const float* vctx_in = vf;
    const float* rc_in   = rvf;

    for (int t = 0; t < 2; t++) {
        float* vctx_out = (t == 0) ? pvctx : pvctx2;
        float* rc_out   = (t == 0) ? prc   : prc2;

        // ---- node side ----
        ewise_mul4<<<(NN * DC4) / 256, 256>>>((const float4*)vf, (const float4*)vctx_in,
                                              (float4*)pvprod, NN * DC4);
        gemm_small(vf,      D, pWjA,            D,     pvj, D, D, 0);
        gemm_small(vctx_in, D, pWjB,            D,     pvj, D, D, 1);
        gemm_small(pvprod,  D, W_joint + 2 * D, 4 * D, pvj, D, D, 1);

        gemm_small(pvj, D, W_ru,         3 * D, pvjWs, D, D, 0);
        gemm_small(pvj, D, W_ru + D,     3 * D, pvjWo, D, D, 0);
        gemm_small(pvj, D, W_sub,        D,     pu,    D, D, 0);
        gemm_small(pvj, D, W_obj,        D,     pv,    D, D, 0);

        // ---- edge side ----
        ewise_mul4<<<(EE * DC4) / 256, 256>>>((const float4*)rvf, (const float4*)rc_in,
                                              (float4*)ptprc, EE * DC4);
        gemm_big(rvf,   D, pW14,          D,     prj, D, EE, D, 0);
        gemm_big(rc_in, D, pW24,          D,     prj, D, EE, D, 1);
        gemm_big(ptprc, D, W_rj + 2 * D,  4 * D, prj, D, EE, D, 1);

        gemm_big(prj, D, W_ru + 2 * D, 3 * D, prelj, D, EE, D, 0);
        relj_add_nodes<<<(EE * DC4) / 256, 256>>>(eidx, (const float4*)pvjWs,
                                                  (const float4*)pvjWo, (float4*)prelj);

        gemm_big(prelj, D, W_r2s, D, pYs, D, EE, D, 0);
        gemm_big(prelj, D, W_r2o, D, pYo, D, EE, D, 0);

        edge_scores<<<EE, 128>>>(eidx, pu, pv, pYs, pYo, pssbj, psobj);
        softmax_edges<<<128, 128>>>(eidx, pssbj, psobj, pwsbj, pwobj);
        ctx_accum<<<128, 256>>>(eidx, pwsbj, pwobj, (const float4*)prelj,
                                (float4*)pctx1, (float4*)pctx2);

        // ---- updates ----
        gemm_small(vctx_in, D, W_ctx,         3 * D, vctx_out, D, D, 0);
        gemm_small(pctx1,   D, W_ctx + D,     3 * D, vctx_out, D, D, 1);
        gemm_small(pctx2,   D, W_ctx + 2 * D, 3 * D, vctx_out, D, D, 1);

        gemm_big(rc_in, D, W_rctx,     2 * D, rc_out, D, EE, D, 0);
        gemm_big(prelj, D, W_rctx + D, 2 * D, rc_out, D, EE, D, 1);

        vctx_in = vctx_out;
        rc_in   = rc_out;
    }

    // ---- outputs: rel_out (E x D) then v_out (N x D) ----
    float* rel_out = (float*)d_out;
    float* v_out   = (float*)d_out + (size_t)EE * D;

    gemm_big(rvf,   D, W_fac,     2 * D, rel_out, D, EE, D, 0);
    gemm_big(rc_in, D, W_fac + D, 2 * D, rel_out, D, EE, D, 1);

    init_bias<<<(NN * D) / 256, 256>>>(b_node, v_out);
    gemm_small(vf,      D, W_node,     2 * D, v_out, D, D, 1);
    gemm_small(vctx_in, D, W_node + D, 2 * D, v_out, D, D, 1);

    (void)out_size;
}

// round 5
// speedup vs baseline: 1.9787x; 1.9787x over previous
#include <cuda_runtime.h>
#include <cstdint>

#define D    1024
#define NN   64
#define EE   1024
#define DC4  (D/4)
#define ES   (6*D)     // edge mega-row stride: [tprc | t | rc | relj | Ys | Yo]
#define NS   (5*D)     // node mega-row stride: [vprod | vf | vctx | ctx1 | ctx2]

// ---------------- scratch (no allocations allowed) ----------------
__device__ float g_E[2][EE*ES];          // 50 MB ping-pong edge buffers
__device__ float g_Nb[2][NN*NS];
__device__ float g_rjm[EE*D];
__device__ float g_vj[NN*D], g_vjWs[NN*D], g_vjWo[NN*D], g_u[NN*D], g_vv[NN*D];
__device__ float g_Wcat1[D*3*D];         // [W3 | W1+W4 | W2-W4] for rj
__device__ float g_Wvjcat[D*3*D];        // [W3 | W1-W4 | W2+W4] for vj
__device__ float g_Wr2cat[2*D*D];        // [W_r2s ; W_r2o] stacked
__device__ float g_part[4*NN*D];         // split-K partials (max KS=4)
__device__ float g_ssbj[EE], g_sobj[EE], g_wsbj[EE], g_wobj[EE];

// =======================================================================
// Big GEMM: C[m,n] = sum_k A[m,k]*B[n,k]. Double-buffered smem + register
// prefetch. Optional fused epilogue: if eidx != null, adds
// nodeS[i(e),n] + nodeO[j(e),n] to row e (relj construction).
// =======================================================================
template<int BM,int BN,int BK,int TM,int TN>
__global__ void __launch_bounds__(256) gemm_nt_big(
    const float* __restrict__ A, int lda,
    const float* __restrict__ B, int ldb,
    float* __restrict__ C, int ldc, int K,
    const int* __restrict__ eidx,
    const float* __restrict__ nodeS, const float* __restrict__ nodeO)
{
    __shared__ float As[2][BK][BM];
    __shared__ float Bs[2][BK][BN];
    const int tid = threadIdx.x;
    const int tx  = tid % (BN/TN);
    const int ty  = tid / (BN/TN);
    const int bm0 = blockIdx.y*BM, bn0 = blockIdx.x*BN;
    constexpr int AV = BM*BK/(256*4);
    constexpr int BV = BN*BK/(256*4);
    float4 pa[AV], pb[BV];

    float acc[TM][TN];
#pragma unroll
    for (int i=0;i<TM;i++)
#pragma unroll
        for (int j=0;j<TN;j++) acc[i][j]=0.f;

    // prologue: tile 0
#pragma unroll
    for (int v=0; v<AV; v++){ int idx = tid*4 + v*1024; int lr=idx/BK, lc=idx%BK;
        pa[v] = *(const float4*)(A + (size_t)(bm0+lr)*lda + lc); }
#pragma unroll
    for (int v=0; v<BV; v++){ int idx = tid*4 + v*1024; int lr=idx/BK, lc=idx%BK;
        pb[v] = *(const float4*)(B + (size_t)(bn0+lr)*ldb + lc); }
#pragma unroll
    for (int v=0; v<AV; v++){ int idx=tid*4+v*1024; int lr=idx/BK, lc=idx%BK;
        As[0][lc][lr]=pa[v].x; As[0][lc+1][lr]=pa[v].y; As[0][lc+2][lr]=pa[v].z; As[0][lc+3][lr]=pa[v].w; }
#pragma unroll
    for (int v=0; v<BV; v++){ int idx=tid*4+v*1024; int lr=idx/BK, lc=idx%BK;
        Bs[0][lc][lr]=pb[v].x; Bs[0][lc+1][lr]=pb[v].y; Bs[0][lc+2][lr]=pb[v].z; Bs[0][lc+3][lr]=pb[v].w; }
    __syncthreads();

    const int nk = K/BK;
    for (int kb=0; kb<nk; kb++){
        const int cur = kb & 1;
        if (kb+1 < nk){
            const int k0 = (kb+1)*BK;
#pragma unroll
            for (int v=0; v<AV; v++){ int idx = tid*4 + v*1024; int lr=idx/BK, lc=idx%BK;
                pa[v] = *(const float4*)(A + (size_t)(bm0+lr)*lda + k0+lc); }
#pragma unroll
            for (int v=0; v<BV; v++){ int idx = tid*4 + v*1024; int lr=idx/BK, lc=idx%BK;
                pb[v] = *(const float4*)(B + (size_t)(bn0+lr)*ldb + k0+lc); }
        }
#pragma unroll
        for (int k=0;k<BK;k++){
            float a[TM], b[TN];
#pragma unroll
            for (int i=0;i<TM;i+=4) *(float4*)&a[i] = *(const float4*)&As[cur][k][ty*TM+i];
#pragma unroll
            for (int j=0;j<TN;j+=4) *(float4*)&b[j] = *(const float4*)&Bs[cur][k][tx*TN+j];
#pragma unroll
            for (int i=0;i<TM;i++)
#pragma unroll
                for (int j=0;j<TN;j++) acc[i][j] += a[i]*b[j];
        }
        if (kb+1 < nk){
            const int nxt = cur^1;
#pragma unroll
            for (int v=0; v<AV; v++){ int idx=tid*4+v*1024; int lr=idx/BK, lc=idx%BK;
                As[nxt][lc][lr]=pa[v].x; As[nxt][lc+1][lr]=pa[v].y; As[nxt][lc+2][lr]=pa[v].z; As[nxt][lc+3][lr]=pa[v].w; }
#pragma unroll
            for (int v=0; v<BV; v++){ int idx=tid*4+v*1024; int lr=idx/BK, lc=idx%BK;
                Bs[nxt][lc][lr]=pb[v].x; Bs[nxt][lc+1][lr]=pb[v].y; Bs[nxt][lc+2][lr]=pb[v].z; Bs[nxt][lc+3][lr]=pb[v].w; }
            __syncthreads();
        }
    }

#pragma unroll
    for (int i=0;i<TM;i++){
        const int row = bm0 + ty*TM + i;
        int ni=0, nj=0;
        if (eidx){ int idx = eidx[row]; ni = idx>>6; nj = idx&63; }
#pragma unroll
        for (int j=0;j<TN;j+=4){
            const int col = bn0 + tx*TN + j;
            float4 o; o.x=acc[i][j+0]; o.y=acc[i][j+1]; o.z=acc[i][j+2]; o.w=acc[i][j+3];
            if (eidx){
                float4 s = *(const float4*)(nodeS + (size_t)ni*D + col);
                float4 t = *(const float4*)(nodeO + (size_t)nj*D + col);
                o.x += s.x+t.x; o.y += s.y+t.y; o.z += s.z+t.z; o.w += s.w+t.w;
            }
            *(float4*)(C + (size_t)row*ldc + col) = o;
        }
    }
}

// =======================================================================
// Small GEMM (M=64) : batched over z (different B,C) and split-K over
// blockIdx.y (partials to g_part, reduced separately).
// =======================================================================
struct SD { const float* B; int ldb; float* C; int ldc; };
struct SD4 { SD d[4]; };

template<int BN,int TM,int TN>
__global__ void __launch_bounds__(128) gemm_nt_64(
    const float* __restrict__ A, int lda, SD4 ds, int K,
    float* __restrict__ part)
{
    constexpr int BM = 64, BK = 16;
    __shared__ float As[2][BK][BM];
    __shared__ float Bs[2][BK][BN];
    const int tid = threadIdx.x;
    const int tx  = tid % (BN/TN);
    const int ty  = tid / (BN/TN);
    const int bn0 = blockIdx.x*BN;
    const float* __restrict__ B = ds.d[blockIdx.z].B;
    const int ldb = ds.d[blockIdx.z].ldb;
    const int Kc  = K / gridDim.y;
    const int kbase = blockIdx.y * Kc;
    constexpr int AV = BM*BK/(128*4);
    constexpr int BV = BN*BK/(128*4);
    float4 pa[AV], pb[BV];

    float acc[TM][TN];
#pragma unroll
    for (int i=0;i<TM;i++)
#pragma unroll
        for (int j=0;j<TN;j++) acc[i][j]=0.f;

#pragma unroll
    for (int v=0; v<AV; v++){ int idx = tid*4 + v*512; int lr=idx/BK, lc=idx%BK;
        pa[v] = *(const float4*)(A + (size_t)lr*lda + kbase+lc); }
#pragma unroll
    for (int v=0; v<BV; v++){ int idx = tid*4 + v*512; int lr=idx/BK, lc=idx%BK;
        pb[v] = *(const float4*)(B + (size_t)(bn0+lr)*ldb + kbase+lc); }
#pragma unroll
    for (int v=0; v<AV; v++){ int idx=tid*4+v*512; int lr=idx/BK, lc=idx%BK;
        As[0][lc][lr]=pa[v].x; As[0][lc+1][lr]=pa[v].y; As[0][lc+2][lr]=pa[v].z; As[0][lc+3][lr]=pa[v].w; }
#pragma unroll
    for (int v=0; v<BV; v++){ int idx=tid*4+v*512; int lr=idx/BK, lc=idx%BK;
        Bs[0][lc][lr]=pb[v].x; Bs[0][lc+1][lr]=pb[v].y; Bs[0][lc+2][lr]=pb[v].z; Bs[0][lc+3][lr]=pb[v].w; }
    __syncthreads();

    const int nk = Kc/BK;
    for (int kb=0; kb<nk; kb++){
        const int cur = kb & 1;
        if (kb+1 < nk){
            const int k0 = kbase + (kb+1)*BK;
#pragma unroll
            for (int v=0; v<AV; v++){ int idx = tid*4 + v*512; int lr=idx/BK, lc=idx%BK;
                pa[v] = *(const float4*)(A + (size_t)lr*lda + k0+lc); }
#pragma unroll
            for (int v=0; v<BV; v++){ int idx = tid*4 + v*512; int lr=idx/BK, lc=idx%BK;
                pb[v] = *(const float4*)(B + (size_t)(bn0+lr)*ldb + k0+lc); }
        }
#pragma unroll
        for (int k=0;k<BK;k++){
            float a[TM], b[TN];
#pragma unroll
            for (int i=0;i<TM;i+=4) *(float4*)&a[i] = *(const float4*)&As[cur][k][ty*TM+i];
#pragma unroll
            for (int j=0;j<TN;j++) b[j] = Bs[cur][k][tx*TN+j];
#pragma unroll
            for (int i=0;i<TM;i++)
#pragma unroll
                for (int j=0;j<TN;j++) acc[i][j] += a[i]*b[j];
        }
        if (kb+1 < nk){
            const int nxt = cur^1;
#pragma unroll
            for (int v=0; v<AV; v++){ int idx=tid*4+v*512; int lr=idx/BK, lc=idx%BK;
                As[nxt][lc][lr]=pa[v].x; As[nxt][lc+1][lr]=pa[v].y; As[nxt][lc+2][lr]=pa[v].z; As[nxt][lc+3][lr]=pa[v].w; }
#pragma unroll
            for (int v=0; v<BV; v++){ int idx=tid*4+v*512; int lr=idx/BK, lc=idx%BK;
                Bs[nxt][lc][lr]=pb[v].x; Bs[nxt][lc+1][lr]=pb[v].y; Bs[nxt][lc+2][lr]=pb[v].z; Bs[nxt][lc+3][lr]=pb[v].w; }
            __syncthreads();
        }
    }

    if (gridDim.y > 1){
        const int Ntot = gridDim.x*BN;
        float* P = part + (size_t)(blockIdx.z*gridDim.y + blockIdx.y)*64*Ntot;
#pragma unroll
        for (int i=0;i<TM;i++){
            const int row = ty*TM+i;
#pragma unroll
            for (int j=0;j<TN;j++)
                P[(size_t)row*Ntot + bn0 + tx*TN + j] = acc[i][j];
        }
    } else {
        float* C = ds.d[blockIdx.z].C; const int ldc = ds.d[blockIdx.z].ldc;
#pragma unroll
        for (int i=0;i<TM;i++){
            const int row = ty*TM+i;
#pragma unroll
            for (int j=0;j<TN;j++)
                C[(size_t)row*ldc + bn0 + tx*TN + j] = acc[i][j];
        }
    }
}

// deterministic fixed-order split-K reduce (+ optional bias)
__global__ void reduce_part(const float* __restrict__ part, int ks, int Ntot,
                            float* __restrict__ out, int ldc,
                            const float* __restrict__ bias)
{
    int gid = blockIdx.x*blockDim.x + threadIdx.x;   // 64*Ntot
    int m = gid / Ntot, n = gid % Ntot;
    float s = bias ? bias[n] : 0.f;
    for (int k=0;k<ks;k++) s += part[(size_t)k*64*Ntot + (size_t)m*Ntot + n];
    out[(size_t)m*ldc + n] = s;
}

// ---------------- small kernels ----------------
__global__ void prep_cat(const float* __restrict__ Wrj, const float* __restrict__ Wj,
                         float* __restrict__ Wcat1, float* __restrict__ Wvjcat)
{
    int gid = blockIdx.x*blockDim.x + threadIdx.x;   // D*3D
    int o = gid / (3*D), c = gid % (3*D);
    int sl = c / D, k = c % D;
    const float* r = Wrj + (size_t)o*4*D;
    const float* j = Wj  + (size_t)o*4*D;
    float v1, v2;
    if (sl == 0)      { v1 = r[2*D+k];            v2 = j[2*D+k]; }
    else if (sl == 1) { v1 = r[k] + r[3*D+k];     v2 = j[k] - j[3*D+k]; }
    else              { v1 = r[D+k] - r[3*D+k];   v2 = j[D+k] + j[3*D+k]; }
    Wcat1[gid] = v1; Wvjcat[gid] = v2;
}

__global__ void prep_r2cat(const float* __restrict__ Wr2s, const float* __restrict__ Wr2o,
                           float* __restrict__ out)
{
    int gid = blockIdx.x*blockDim.x + threadIdx.x;   // 2*D*D
    out[gid] = (gid < D*D) ? Wr2s[gid] : Wr2o[gid - D*D];
}

// copy dense (rows x D) into strided slice
__global__ void copy_slice(const float4* __restrict__ src, float4* __restrict__ dst, int rs4)
{
    int gid = blockIdx.x*blockDim.x + threadIdx.x;   // rows*DC4
    int r = gid / DC4, c = gid % DC4;
    dst[(size_t)r*rs4 + c] = src[gid];
}

// o = a*b elementwise, all strided slices of same mega-buffer
__global__ void mul_slice(const float4* __restrict__ a, const float4* __restrict__ b,
                          float4* __restrict__ o, int rs4)
{
    int gid = blockIdx.x*blockDim.x + threadIdx.x;   // rows*DC4
    int r = gid / DC4, c = gid % DC4;
    size_t off = (size_t)r*rs4 + c;
    float4 x = a[off], y = b[off];
    float4 v; v.x=x.x*y.x; v.y=x.y*y.y; v.z=x.z*y.z; v.w=x.w*y.w;
    o[off] = v;
}

// scores: s_sbj[e] = <u[i(e)], Ys[e]>/32 ; s_obj[e] = <v[j(e)], Yo[e]>/32
__global__ void edge_scores(const int* __restrict__ eidx,
                            const float* __restrict__ u, const float* __restrict__ v,
                            const float* __restrict__ Eb,
                            float* __restrict__ s_sbj, float* __restrict__ s_obj)
{
    int e = blockIdx.x;
    int idx = eidx[e];
    int i = idx >> 6, j = idx & 63;
    const float4* u4  = (const float4*)(u + (size_t)i*D);
    const float4* v4  = (const float4*)(v + (size_t)j*D);
    const float4* ys4 = (const float4*)(Eb + (size_t)e*ES + 4*D);
    const float4* yo4 = (const float4*)(Eb + (size_t)e*ES + 5*D);
    float ss=0.f, so=0.f;
    for (int c = threadIdx.x; c < DC4; c += blockDim.x){
        float4 a=u4[c], b=ys4[c];
        ss += a.x*b.x + a.y*b.y + a.z*b.z + a.w*b.w;
        float4 a2=v4[c], b2=yo4[c];
        so += a2.x*b2.x + a2.y*b2.y + a2.z*b2.z + a2.w*b2.w;
    }
#pragma unroll
    for (int off=16; off; off>>=1){
        ss += __shfl_xor_sync(0xffffffffu, ss, off);
        so += __shfl_xor_sync(0xffffffffu, so, off);
    }
    __shared__ float shs[4], sho[4];
    int warp = threadIdx.x>>5, lane = threadIdx.x&31;
    if (lane==0){ shs[warp]=ss; sho[warp]=so; }
    __syncthreads();
    if (threadIdx.x==0){
        s_sbj[e] = (shs[0]+shs[1]+shs[2]+shs[3]) * 0.03125f;
        s_obj[e] = (sho[0]+sho[1]+sho[2]+sho[3]) * 0.03125f;
    }
}

__global__ void softmax_edges(const int* __restrict__ eidx,
                              const float* __restrict__ s_sbj, const float* __restrict__ s_obj,
                              float* __restrict__ w_sbj, float* __restrict__ w_obj)
{
    int mode = blockIdx.x >> 6;
    int node = blockIdx.x & 63;
    const float* s = mode ? s_obj : s_sbj;
    float* w = mode ? w_obj : w_sbj;
    int tid = threadIdx.x;    // 128
    __shared__ float red[128];
    float m = -1e30f;
    for (int e=tid; e<EE; e+=128){
        int idx = eidx[e];
        int ne = mode ? (idx&63) : (idx>>6);
        if (ne==node) m = fmaxf(m, s[e]);
    }
    red[tid]=m; __syncthreads();
    for (int st=64; st; st>>=1){ if (tid<st) red[tid]=fmaxf(red[tid],red[tid+st]); __syncthreads(); }
    float mm = red[0]; __syncthreads();
    float z = 0.f;
    for (int e=tid; e<EE; e+=128){
        int idx = eidx[e];
        int ne = mode ? (idx&63) : (idx>>6);
        if (ne==node) z += expf(s[e]-mm);
    }
    red[tid]=z; __syncthreads();
    for (int st=64; st; st>>=1){ if (tid<st) red[tid]+=red[tid+st]; __syncthreads(); }
    float inv = 1.f/red[0];
    for (int e=tid; e<EE; e+=128){
        int idx = eidx[e];
        int ne = mode ? (idx&63) : (idx>>6);
        if (ne==node) w[e] = expf(s[e]-mm)*inv;
    }
}

// ctx1[i] = sum_{e: i(e)=i} w_sbj[e]*relj[e]; ctx2[j] likewise (blocks 64..127)
__global__ void ctx_accum(const int* __restrict__ eidx,
                          const float* __restrict__ w_sbj, const float* __restrict__ w_obj,
                          const float* __restrict__ Eb, float* __restrict__ Nb)
{
    int part = blockIdx.x >> 6;
    int node = blockIdx.x & 63;
    int tid = threadIdx.x;    // 256 = DC4
    __shared__ int   se[EE];
    __shared__ float sw[EE];
    for (int e=tid; e<EE; e+=256){
        se[e] = eidx[e];
        sw[e] = part ? w_obj[e] : w_sbj[e];
    }
    __syncthreads();
    float4 acc = make_float4(0.f,0.f,0.f,0.f);
    for (int e=0;e<EE;e++){
        int idx = se[e];
        int ne = part ? (idx&63) : (idx>>6);
        if (ne==node){
            float wt = sw[e];
            float4 r = ((const float4*)(Eb + (size_t)e*ES + 3*D))[tid];
            acc.x += wt*r.x; acc.y += wt*r.y; acc.z += wt*r.z; acc.w += wt*r.w;
        }
    }
    ((float4*)(Nb + (size_t)node*NS + (part ? 4*D : 3*D)))[tid] = acc;
}

// ---------------- host orchestration ----------------
#define BIGGRID(Nn,Mm) dim3((Nn)/64, (Mm)/128)

static inline void big(const float* A,int lda,const float* B,int ldb,
                       float* C,int ldc,int M,int N,int K,
                       const int* eidx=nullptr,const float* nS=nullptr,const float* nO=nullptr)
{
    gemm_nt_big<128,64,16,8,4><<<BIGGRID(N,M),256>>>(A,lda,B,ldb,C,ldc,K,eidx,nS,nO);
}

extern "C" void kernel_launch(void* const* d_in, const int* in_sizes, int n_in,
                              void* d_out, int out_size)
{
    (void)in_sizes; (void)n_in; (void)out_size;
    const float* vf   = (const float*)d_in[0];
    const float* rvf  = (const float*)d_in[1];
    const int*   eidx = (const int*)  d_in[4];
    const float* W_sub   = (const float*)d_in[5];
    const float* W_obj   = (const float*)d_in[6];
    const float* W_r2s   = (const float*)d_in[7];
    const float* W_r2o   = (const float*)d_in[8];
    const float* W_joint = (const float*)d_in[9];  (void)W_joint;
    const float* W_ctx   = (const float*)d_in[10];
    const float* W_ru    = (const float*)d_in[11];
    const float* W_rj    = (const float*)d_in[12];
    const float* W_rctx  = (const float*)d_in[13];
    const float* W_node  = (const float*)d_in[14];
    const float* b_node  = (const float*)d_in[15];
    const float* W_fac   = (const float*)d_in[16];

    void* p;
    cudaGetSymbolAddress(&p, g_E);      float* Eb0 = (float*)p;
    float* Eb[2] = { Eb0, Eb0 + (size_t)EE*ES };
    cudaGetSymbolAddress(&p, g_Nb);     float* Nb0 = (float*)p;
    float* Nb[2] = { Nb0, Nb0 + (size_t)NN*NS };
    cudaGetSymbolAddress(&p, g_rjm);    float* prj   = (float*)p;
    cudaGetSymbolAddress(&p, g_vj);     float* pvj   = (float*)p;
    cudaGetSymbolAddress(&p, g_vjWs);   float* pvjWs = (float*)p;
    cudaGetSymbolAddress(&p, g_vjWo);   float* pvjWo = (float*)p;
    cudaGetSymbolAddress(&p, g_u);      float* pu    = (float*)p;
    cudaGetSymbolAddress(&p, g_vv);     float* pv    = (float*)p;
    cudaGetSymbolAddress(&p, g_Wcat1);  float* pW1   = (float*)p;
    cudaGetSymbolAddress(&p, g_Wvjcat); float* pW2   = (float*)p;
    cudaGetSymbolAddress(&p, g_Wr2cat); float* pW3   = (float*)p;
    cudaGetSymbolAddress(&p, g_part);   float* ppart = (float*)p;
    cudaGetSymbolAddress(&p, g_ssbj);   float* pss   = (float*)p;
    cudaGetSymbolAddress(&p, g_sobj);   float* pso   = (float*)p;
    cudaGetSymbolAddress(&p, g_wsbj);   float* pws   = (float*)p;
    cudaGetSymbolAddress(&p, g_wobj);   float* pwo   = (float*)p;

    // ---- prep: folded weights + seed mega-buffers ----
    prep_cat<<<(D*3*D)/256,256>>>(W_rj, (const float*)d_in[9], pW1, pW2);
    prep_r2cat<<<(2*D*D)/256,256>>>(W_r2s, W_r2o, pW3);
    copy_slice<<<(EE*DC4)/256,256>>>((const float4*)rvf, (float4*)(Eb[0]+D),   ES/4);
    copy_slice<<<(EE*DC4)/256,256>>>((const float4*)rvf, (float4*)(Eb[0]+2*D), ES/4);
    copy_slice<<<(EE*DC4)/256,256>>>((const float4*)rvf, (float4*)(Eb[1]+D),   ES/4);
    copy_slice<<<(NN*DC4)/256,256>>>((const float4*)vf,  (float4*)(Nb[0]+D),   NS/4);
    copy_slice<<<(NN*DC4)/256,256>>>((const float4*)vf,  (float4*)(Nb[0]+2*D), NS/4);
    copy_slice<<<(NN*DC4)/256,256>>>((const float4*)vf,  (float4*)(Nb[1]+D),   NS/4);

    SD4 dvj{};   dvj.d[0]  = { pW2, 3*D, nullptr, 0 };
    SD4 d4;      d4.d[0] = { W_ru,     3*D, pvjWs, D };
                 d4.d[1] = { W_ru+D,   3*D, pvjWo, D };
                 d4.d[2] = { W_sub,    D,   pu,    D };
                 d4.d[3] = { W_obj,    D,   pv,    D };
    SD4 dctx{};  dctx.d[0] = { W_ctx, 3*D, nullptr, 0 };
    SD4 dnode{}; dnode.d[0] = { W_node, 2*D, nullptr, 0 };

    for (int t = 0; t < 2; t++){
        float* Ec = Eb[t&1];  float* En = Eb[(t&1)^1];
        float* Nc = Nb[t&1];  float* Nn = Nb[(t&1)^1];

        // elementwise products into slice 0
        mul_slice<<<(EE*DC4)/256,256>>>((const float4*)(Ec+D), (const float4*)(Ec+2*D),
                                        (float4*)Ec, ES/4);
        mul_slice<<<(NN*DC4)/256,256>>>((const float4*)(Nc+D), (const float4*)(Nc+2*D),
                                        (float4*)Nc, NS/4);

        // vj = [vprod|vf|vctx] @ Wvjcat^T   (split-K 4)
        gemm_nt_64<32,8,2><<<dim3(32,4,1),128>>>(Nc, NS, dvj, 3*D, ppart);
        reduce_part<<<(NN*D)/256,256>>>(ppart, 4, D, pvj, D, nullptr);

        // batched: vjWs, vjWo, u, v
        gemm_nt_64<32,8,2><<<dim3(32,1,4),128>>>(pvj, D, d4, D, ppart);

        // rj = [tprc|t|rc] @ Wcat1^T
        big(Ec, ES, pW1, 3*D, prj, D, EE, D, 3*D);
        // relj = rj @ Wr^T + vjWs[i] + vjWo[j]   (fused epilogue)
        big(prj, D, W_ru+2*D, 3*D, Ec+3*D, ES, EE, D, D, eidx, pvjWs, pvjWo);
        // [Ys|Yo] = relj @ [W_r2s;W_r2o]^T
        big(Ec+3*D, ES, pW3, D, Ec+4*D, ES, EE, 2*D, D);

        edge_scores<<<EE,128>>>(eidx, pu, pv, Ec, pss, pso);
        softmax_edges<<<128,128>>>(eidx, pss, pso, pws, pwo);
        ctx_accum<<<128,256>>>(eidx, pws, pwo, Ec, Nc);

        // vctx_next = [vctx|ctx1|ctx2] @ W_ctx^T   (split-K 4)
        gemm_nt_64<32,8,2><<<dim3(32,4,1),128>>>(Nc+2*D, NS, dctx, 3*D, ppart);
        reduce_part<<<(NN*D)/256,256>>>(ppart, 4, D, Nn+2*D, NS, nullptr);

        // rc_next = [rc|relj] @ W_rctx^T
        big(Ec+2*D, ES, W_rctx, 2*D, En+2*D, ES, EE, D, 2*D);
    }

    // ---- outputs ----
    float* rel_out = (float*)d_out;
    float* v_out   = (float*)d_out + (size_t)EE*D;

    // rel_out = [t|rc_final] @ W_fac^T   (rc_final landed in Eb[0] slice 2)
    big(Eb[0]+D, ES, W_fac, 2*D, rel_out, D, EE, D, 2*D);

    // v_out = [vf|vctx_final] @ W_node^T + b   (vctx_final in Nb[0] slice 2)
    gemm_nt_64<32,8,2><<<dim3(32,2,1),128>>>(Nb[0]+D, NS, dnode, 2*D, ppart);
    reduce_part<<<(NN*D)/256,256>>>(ppart, 2, D, v_out, D, b_node);
}